// round 15
// baseline (speedup 1.0000x reference)
#include <cuda_runtime.h>
#include <cuda_fp16.h>
#include <math.h>
#include <stdint.h>

#define NB   128
#define SEQL 197
#define NPAT 196
#define HD   768
#define NH   12
#define DH   64
#define LN_EPS 1e-5f
#define NA   (NB * NPAT * HD)   // 19267584 image elems
#define NW   (HD * HD)

// ---------------- scratch (static device globals; no allocs) ----------------
static __device__ float g_tokens[NB * SEQL * HD];          // 77.4 MB
static __device__ float g_pos[SEQL * HD];
static __device__ float g_mean[NB];
static __device__ float g_rstd[NB];
static __device__ float g_sum[NB];
static __device__ float g_sumsq[NB];
static __device__ __half g_Ah[NA];                          // fp16 images
static __device__ __half g_Wh[NW];                          // fp16 W_map

// ================= helpers =================
__device__ __forceinline__ uint32_t smem_u32(const void* p) {
    uint32_t a;
    asm("{ .reg .u64 t; cvta.to.shared.u64 t, %1; cvt.u32.u64 %0, t; }" : "=r"(a) : "l"(p));
    return a;
}
#define LDSM4(r, addr) \
    asm volatile("ldmatrix.sync.aligned.m8n8.x4.shared.b16 {%0,%1,%2,%3}, [%4];" \
        : "=r"((r)[0]), "=r"((r)[1]), "=r"((r)[2]), "=r"((r)[3]) : "r"(addr))

__device__ __forceinline__ void mma_f16(float* c, const uint32_t* a, const uint32_t* b) {
    asm volatile("mma.sync.aligned.m16n8k16.row.col.f32.f16.f16.f32 "
        "{%0,%1,%2,%3}, {%4,%5,%6,%7}, {%8,%9}, {%0,%1,%2,%3};"
        : "+f"(c[0]), "+f"(c[1]), "+f"(c[2]), "+f"(c[3])
        : "r"(a[0]), "r"(a[1]), "r"(a[2]), "r"(a[3]), "r"(b[0]), "r"(b[1]));
}

__device__ __forceinline__ uint32_t pack_h_f(float x, float y) {
    __half2 t = __floats2half2_rn(x, y);
    return *(uint32_t*)&t;
}
__device__ __forceinline__ uint2 cvt_f4(float4 v) {
    uint2 r;
    r.x = pack_h_f(v.x, v.y);
    r.y = pack_h_f(v.z, v.w);
    return r;
}
__device__ __forceinline__ uint32_t ex2_h2(uint32_t y) {
    uint32_t r;
    asm("ex2.approx.f16x2 %0, %1;" : "=r"(r) : "r"(y));
    return r;
}
__device__ __forceinline__ uint32_t hmul2_u(uint32_t a, uint32_t b) {
    __half2 t = __hmul2(*(__half2*)&a, *(__half2*)&b);
    return *(uint32_t*)&t;
}

// ---------------- positional embeddings (+ zero stat accumulators) ----------------
__global__ void pos_kernel() {
    int idx = blockIdx.x * blockDim.x + threadIdx.x;
    if (idx < NB) { g_sum[idx] = 0.f; g_sumsq[idx] = 0.f; }
    if (idx >= SEQL * HD) return;
    int i = idx / HD, j = idx % HD;
    float jf = (float)(j & ~1);
    float denom = powf(10000.0f, jf / (float)HD);
    float arg = (float)i / denom;
    g_pos[idx] = (j & 1) ? cosf(arg) : sinf(arg);
}

// ---------------- class token row (+ stats contribution) ----------------
__global__ __launch_bounds__(256) void cls_kernel(const float* __restrict__ cls) {
    int b = blockIdx.x;
    float s = 0.f, q = 0.f;
    for (int j = threadIdx.x; j < HD; j += 256) {
        float v = cls[j] + g_pos[j];
        g_tokens[(size_t)b * SEQL * HD + j] = v;
        s += v; q += v * v;
    }
#pragma unroll
    for (int o = 16; o; o >>= 1) {
        s += __shfl_xor_sync(0xffffffffu, s, o);
        q += __shfl_xor_sync(0xffffffffu, q, o);
    }
    __shared__ float sh[16];
    int w = threadIdx.x >> 5, l = threadIdx.x & 31;
    if (!l) { sh[w] = s; sh[8 + w] = q; }
    __syncthreads();
    if (threadIdx.x == 0) {
        float S = 0.f, Q = 0.f;
        for (int i = 0; i < 8; i++) { S += sh[i]; Q += sh[8 + i]; }
        atomicAdd(&g_sum[b], S);
        atomicAdd(&g_sumsq[b], Q);
    }
}

// ---------------- fp32 -> fp16 pre-convert (images + W_map) ----------------
__global__ __launch_bounds__(256) void cvt_kernel(const float* __restrict__ A,
                                                  const float* __restrict__ Wm) {
    const int stride = gridDim.x * blockDim.x;
    const int tot4 = (NA + NW) / 4;
    for (int i = blockIdx.x * blockDim.x + threadIdx.x; i < tot4; i += stride) {
        if (i < NA / 4) {
            float4 v = ((const float4*)A)[i];
            *(uint2*)&g_Ah[(size_t)i * 4] = cvt_f4(v);
        } else {
            int j = i - NA / 4;
            float4 v = ((const float4*)Wm)[j];
            *(uint2*)&g_Wh[(size_t)j * 4] = cvt_f4(v);
        }
    }
}

// ---------------- token projection GEMM: fp16 mma + cp.async + frag pipeline --
// C[m,n] = sum_k A[m,k]*W[n,k]; M=25088, N=768, K=768.
// CTA tile 128x128, BK=64, 8 warps (4m x 2n), warp tile 32x64. 2 CTA/SM.
#define KS 72
#define GST (256 * KS)            // halves per stage
#define G_SMEM (3 * GST * 2)      // 110592 bytes

#define GEMM_ISSUE(ktile) do { \
    __half* st_ = sm + ((ktile) % 3) * GST; \
    const int kb_ = (ktile) * 64; \
    _Pragma("unroll") \
    for (int it = 0; it < 8; it++) { \
        int ch = it * 256 + tid; \
        int row = ch >> 3, c8 = ch & 7; \
        const __half* src = (row < 128) \
            ? (g_Ah + (size_t)(m0 + row) * HD + kb_ + c8 * 8) \
            : (g_Wh + (size_t)(n0 + row - 128) * HD + kb_ + c8 * 8); \
        uint32_t dst = smem_u32(&st_[row * KS + c8 * 8]); \
        asm volatile("cp.async.cg.shared.global [%0], [%1], 16;" :: "r"(dst), "l"(src)); \
    } \
} while (0)
#define CP_COMMIT() asm volatile("cp.async.commit_group;" ::: "memory")
#define CP_WAIT1()  asm volatile("cp.async.wait_group 1;" ::: "memory")

#define G_LOADF(aa, bb, k0) do { \
    _Pragma("unroll") \
    for (int mf = 0; mf < 2; mf++) { \
        int r = wm * 32 + mf * 16 + (lane & 15); \
        int ko = (k0) + (lane >> 4) * 8; \
        LDSM4(aa[mf], smem_u32(&st[r * KS + ko])); \
    } \
    _Pragma("unroll") \
    for (int nf2 = 0; nf2 < 4; nf2++) { \
        int r = wn * 64 + nf2 * 16 + (seg >> 1) * 8 + (lane & 7); \
        int ko = (k0) + (seg & 1) * 8; \
        LDSM4(bb[nf2], smem_u32(&st[128 * KS + r * KS + ko])); \
    } \
} while (0)

#define G_MMAF(aa, bb) do { \
    _Pragma("unroll") \
    for (int nf2 = 0; nf2 < 4; nf2++) \
        _Pragma("unroll") \
        for (int mf = 0; mf < 2; mf++) { \
            mma_f16(c[mf][nf2 * 2 + 0], aa[mf], bb[nf2] + 0); \
            mma_f16(c[mf][nf2 * 2 + 1], aa[mf], bb[nf2] + 2); \
        } \
} while (0)

__global__ __launch_bounds__(256, 2) void gemm_tokens_mma(const float* __restrict__ bias) {
    extern __shared__ char smc[];
    __half* sm = (__half*)smc;
    const int tid  = threadIdx.x;
    const int lane = tid & 31, wid = tid >> 5;
    const int wm = wid & 3, wn = wid >> 2;
    const int seg = lane >> 3;
    const int n0 = blockIdx.x * 128;
    const int m0 = blockIdx.y * 128;

    float c[2][8][4] = {};

    GEMM_ISSUE(0); CP_COMMIT();
    GEMM_ISSUE(1); CP_COMMIT();

    for (int kt = 0; kt < 12; kt++) {
        CP_WAIT1();
        __syncthreads();
        if (kt + 2 < 12) GEMM_ISSUE(kt + 2);
        CP_COMMIT();
        __half* st = sm + (kt % 3) * GST;
        uint32_t a0[2][4], b0[4][4], a1[2][4], b1[4][4];
        G_LOADF(a0, b0, 0);
        G_LOADF(a1, b1, 16);
        G_MMAF(a0, b0);
        G_LOADF(a0, b0, 32);
        G_MMAF(a1, b1);
        G_LOADF(a1, b1, 48);
        G_MMAF(a0, b0);
        G_MMAF(a1, b1);
    }

    // epilogue: + bias + pos, scatter; accumulate per-sample stats
    float ssum[2] = {0.f, 0.f}, ssq[2] = {0.f, 0.f};
    const int bbase = m0 / NPAT;
    const bool has2 = ((m0 + 127) / NPAT) != bbase;
#pragma unroll
    for (int mf = 0; mf < 2; mf++) {
#pragma unroll
        for (int half = 0; half < 2; half++) {
            int mg = m0 + wm * 32 + mf * 16 + (lane >> 2) + half * 8;
            int b = mg / NPAT, p = mg % NPAT;
            int slot = b - bbase;
            float* orow = g_tokens + ((size_t)b * SEQL + p + 1) * HD;
            const float* prow = g_pos + (size_t)(p + 1) * HD;
            float ls = 0.f, lq = 0.f;
#pragma unroll
            for (int nf = 0; nf < 8; nf++) {
                int col = n0 + wn * 64 + nf * 8 + (lane & 3) * 2;
                float2 o;
                o.x = c[mf][nf][half * 2 + 0] + bias[col] + prow[col];
                o.y = c[mf][nf][half * 2 + 1] + bias[col + 1] + prow[col + 1];
                *(float2*)(orow + col) = o;
                ls += o.x + o.y;
                lq += o.x * o.x + o.y * o.y;
            }
            ssum[slot] += ls;
            ssq[slot] += lq;
        }
    }
#pragma unroll
    for (int o = 16; o; o >>= 1) {
        ssum[0] += __shfl_xor_sync(0xffffffffu, ssum[0], o);
        ssq[0]  += __shfl_xor_sync(0xffffffffu, ssq[0], o);
        ssum[1] += __shfl_xor_sync(0xffffffffu, ssum[1], o);
        ssq[1]  += __shfl_xor_sync(0xffffffffu, ssq[1], o);
    }
    if (lane == 0) {
        atomicAdd(&g_sum[bbase], ssum[0]);
        atomicAdd(&g_sumsq[bbase], ssq[0]);
        if (has2) {
            atomicAdd(&g_sum[bbase + 1], ssum[1]);
            atomicAdd(&g_sumsq[bbase + 1], ssq[1]);
        }
    }
}

// ---------------- finalize LN stats ----------------
__global__ void finalize_kernel() {
    int b = threadIdx.x;
    if (b < NB) {
        const float n = (float)(SEQL * HD);
        float mean = g_sum[b] / n;
        float var  = g_sumsq[b] / n - mean * mean;
        g_mean[b] = mean;
        g_rstd[b] = rsqrtf(var + LN_EPS);
    }
}

// ---------------- fused QKV + attention: 416 threads = 13 warps ----------------
// Q kept in registers (relayout C-frag -> A-frag); K, Vt staged in smem.
#define NTH  416
#define SEQP 208
#define QKS  72
#define VTS  216
#define FX  0
#define FW  (SEQP * QKS)
#define FK  (SEQP * QKS + 192 * QKS)
#define FVT (FK + SEQP * QKS)
#define FUSED_SMEM ((FVT + 64 * VTS) * 2)

__global__ void __launch_bounds__(NTH, 1) qkv_attn_fused(
    const float* __restrict__ lnw, const float* __restrict__ lnb,
    const float* __restrict__ Wq, const float* __restrict__ bq,
    const float* __restrict__ Wk, const float* __restrict__ bk,
    const float* __restrict__ Wv, const float* __restrict__ bv,
    float* __restrict__ out) {
    extern __shared__ __half fsm[];
    const int tid = threadIdx.x, lane = tid & 31, w = tid >> 5;
    const int seg = lane >> 3;
    const int bh = blockIdx.x, b = bh / NH, h = bh % NH;
    const float mean = g_mean[b], rstd = g_rstd[b];
    const float* tb = g_tokens + (size_t)b * SEQL * HD + h * DH;

    // ---- phase 0: stage X normalized (fp16) and W (fp16) ----
    for (int idx = tid; idx < SEQP * 16; idx += NTH) {
        int s = idx >> 4, d4 = (idx & 15) * 4;
        float4 x = {0.f, 0.f, 0.f, 0.f};
        if (s < SEQL) {
            float4 tv = *(const float4*)(tb + (size_t)s * HD + d4);
            float4 wv = *(const float4*)(lnw + (size_t)s * HD + h * DH + d4);
            float4 bb = *(const float4*)(lnb + (size_t)s * HD + h * DH + d4);
            x.x = (tv.x - mean) * rstd * wv.x + bb.x;
            x.y = (tv.y - mean) * rstd * wv.y + bb.y;
            x.z = (tv.z - mean) * rstd * wv.z + bb.z;
            x.w = (tv.w - mean) * rstd * wv.w + bb.w;
        }
        *(uint2*)&fsm[FX + s * QKS + d4] = cvt_f4(x);
    }
    for (int idx = tid; idx < 3 * 64 * 16; idx += NTH) {
        int m = idx >> 10, rem = idx & 1023;
        int e = rem >> 4, d4 = (rem & 15) * 4;
        const float* Wsrc = (m == 0 ? Wq : (m == 1 ? Wk : Wv)) + (size_t)h * DH * DH;
        float4 v = *(const float4*)(Wsrc + e * DH + d4);
        *(uint2*)&fsm[FW + (m * 64 + e) * QKS + d4] = cvt_f4(v);
    }
    __syncthreads();

    // ---- phase 1: warp w computes q (registers), k, v for tile w ----
    const int mt = w;
    uint32_t qh[4][4];
    {
        uint32_t af[4][4];
#pragma unroll
        for (int ks = 0; ks < 4; ks++) {
            int r = mt * 16 + (lane & 15);
            int ko = ks * 16 + (lane >> 4) * 8;
            LDSM4(af[ks], smem_u32(&fsm[FX + r * QKS + ko]));
        }
        // m = 0: q -> registers (relayout C-frag to A-frag, bias + 1/8 applied)
        {
            float c0[8][4] = {};
#pragma unroll
            for (int ks = 0; ks < 4; ks++) {
#pragma unroll
                for (int nf2 = 0; nf2 < 4; nf2++) {
                    int r = nf2 * 16 + (seg >> 1) * 8 + (lane & 7);
                    int ko = ks * 16 + (seg & 1) * 8;
                    uint32_t bfr[4];
                    LDSM4(bfr, smem_u32(&fsm[FW + r * QKS + ko]));
                    mma_f16(c0[nf2 * 2 + 0], af[ks], bfr + 0);
                    mma_f16(c0[nf2 * 2 + 1], af[ks], bfr + 2);
                }
            }
            const float* biasq = bq + h * DH;
#pragma unroll
            for (int ksx = 0; ksx < 4; ksx++) {
                int e0 = (2 * ksx) * 8 + (lane & 3) * 2;
                int e1 = e0 + 8;
                float bz0 = biasq[e0], bz1 = biasq[e0 + 1];
                float bz2 = biasq[e1], bz3 = biasq[e1 + 1];
                qh[ksx][0] = pack_h_f((c0[2 * ksx][0] + bz0) * 0.125f, (c0[2 * ksx][1] + bz1) * 0.125f);
                qh[ksx][1] = pack_h_f((c0[2 * ksx][2] + bz0) * 0.125f, (c0[2 * ksx][3] + bz1) * 0.125f);
                qh[ksx][2] = pack_h_f((c0[2 * ksx + 1][0] + bz2) * 0.125f, (c0[2 * ksx + 1][1] + bz3) * 0.125f);
                qh[ksx][3] = pack_h_f((c0[2 * ksx + 1][2] + bz2) * 0.125f, (c0[2 * ksx + 1][3] + bz3) * 0.125f);
            }
        }
        // m = 1 (K), m = 2 (V^T)
#pragma unroll
        for (int m = 1; m < 3; m++) {
            float c[8][4] = {};
#pragma unroll
            for (int ks = 0; ks < 4; ks++) {
#pragma unroll
                for (int nf2 = 0; nf2 < 4; nf2++) {
                    int r = m * 64 + nf2 * 16 + (seg >> 1) * 8 + (lane & 7);
                    int ko = ks * 16 + (seg & 1) * 8;
                    uint32_t bfr[4];
                    LDSM4(bfr, smem_u32(&fsm[FW + r * QKS + ko]));
                    mma_f16(c[nf2 * 2 + 0], af[ks], bfr + 0);
                    mma_f16(c[nf2 * 2 + 1], af[ks], bfr + 2);
                }
            }
            const float* bias = (m == 1 ? bk : bv) + h * DH;
            int r0 = mt * 16 + (lane >> 2);
#pragma unroll
            for (int half = 0; half < 2; half++) {
                int r = r0 + half * 8;   // < 208; padded rows hold bias (inert)
#pragma unroll
                for (int nf = 0; nf < 8; nf++) {
                    int e = nf * 8 + (lane & 3) * 2;
                    float v0 = c[nf][half * 2 + 0] + bias[e];
                    float v1 = c[nf][half * 2 + 1] + bias[e + 1];
                    if (m == 1) {
                        *(uint32_t*)&fsm[FK + r * QKS + e] = pack_h_f(v0, v1);
                    } else {
                        fsm[FVT + e * VTS + r] = __float2half_rn(v0);
                        fsm[FVT + (e + 1) * VTS + r] = __float2half_rn(v1);
                    }
                }
            }
        }
    }
    __syncthreads();

    // ---- phase 2: attention, one m-tile per warp ----
    {
        float c[26][4];
#pragma unroll
        for (int nf = 0; nf < 26; nf++)
            c[nf][0] = c[nf][1] = c[nf][2] = c[nf][3] = 0.f;

        // S = Qs * K^T (Q a-frags from registers)
#pragma unroll
        for (int ksx = 0; ksx < 4; ksx++) {
#pragma unroll
            for (int nf2 = 0; nf2 < 13; nf2++) {
                int r = nf2 * 16 + (seg >> 1) * 8 + (lane & 7);
                int co = ksx * 16 + (seg & 1) * 8;
                uint32_t t4[4];
                LDSM4(t4, smem_u32(&fsm[FK + r * QKS + co]));
                mma_f16(c[2 * nf2 + 0], qh[ksx], t4 + 0);
                mma_f16(c[2 * nf2 + 1], qh[ksx], t4 + 2);
            }
        }

        // mask padded columns (cols >= 197)
        {
            int cb = (lane & 3) * 2;
            if (192 + cb >= SEQL) { c[24][0] = -1e30f; c[24][2] = -1e30f; }
            if (193 + cb >= SEQL) { c[24][1] = -1e30f; c[24][3] = -1e30f; }
            c[25][0] = c[25][1] = c[25][2] = c[25][3] = -1e30f;
        }

        // softmax: row max, then P = 2^(L2E*(s - mx)) via ex2.approx.f16x2
        float mx0 = -1e30f, mx1 = -1e30f;
#pragma unroll
        for (int nf = 0; nf < 26; nf++) {
            mx0 = fmaxf(mx0, fmaxf(c[nf][0], c[nf][1]));
            mx1 = fmaxf(mx1, fmaxf(c[nf][2], c[nf][3]));
        }
        mx0 = fmaxf(mx0, __shfl_xor_sync(0xffffffffu, mx0, 1));
        mx0 = fmaxf(mx0, __shfl_xor_sync(0xffffffffu, mx0, 2));
        mx1 = fmaxf(mx1, __shfl_xor_sync(0xffffffffu, mx1, 1));
        mx1 = fmaxf(mx1, __shfl_xor_sync(0xffffffffu, mx1, 2));

        const float L2E = 1.4426950408889634f;
        const float b0 = mx0 * L2E, b1 = mx1 * L2E;
        uint32_t ph[26][2];
        float s0 = 0.f, s1 = 0.f;
#pragma unroll
        for (int nf = 0; nf < 26; nf++) {
            uint32_t y0 = pack_h_f(fmaf(c[nf][0], L2E, -b0), fmaf(c[nf][1], L2E, -b0));
            uint32_t y1 = pack_h_f(fmaf(c[nf][2], L2E, -b1), fmaf(c[nf][3], L2E, -b1));
            ph[nf][0] = ex2_h2(y0);
            ph[nf][1] = ex2_h2(y1);
            float2 f0 = __half22float2(*(__half2*)&ph[nf][0]);
            float2 f1 = __half22float2(*(__half2*)&ph[nf][1]);
            s0 += f0.x + f0.y;
            s1 += f1.x + f1.y;
        }
        s0 += __shfl_xor_sync(0xffffffffu, s0, 1);
        s0 += __shfl_xor_sync(0xffffffffu, s0, 2);
        s1 += __shfl_xor_sync(0xffffffffu, s1, 1);
        s1 += __shfl_xor_sync(0xffffffffu, s1, 2);
        float inv0 = 1.0f / s0, inv1 = 1.0f / s1;
        uint32_t ih0 = pack_h_f(inv0, inv0);
        uint32_t ih1 = pack_h_f(inv1, inv1);

        // O = P * V^T
        float o[8][4];
#pragma unroll
        for (int ne = 0; ne < 8; ne++)
            o[ne][0] = o[ne][1] = o[ne][2] = o[ne][3] = 0.f;

#pragma unroll
        for (int kt = 0; kt < 13; kt++) {
            uint32_t pa[4];
            pa[0] = hmul2_u(ph[2 * kt][0], ih0);
            pa[1] = hmul2_u(ph[2 * kt][1], ih1);
            pa[2] = hmul2_u(ph[2 * kt + 1][0], ih0);
            pa[3] = hmul2_u(ph[2 * kt + 1][1], ih1);
#pragma unroll
            for (int ne2 = 0; ne2 < 4; ne2++) {
                int r = ne2 * 16 + (seg >> 1) * 8 + (lane & 7);
                int co = kt * 16 + (seg & 1) * 8;
                uint32_t t4[4];
                LDSM4(t4, smem_u32(&fsm[FVT + r * VTS + co]));
                mma_f16(o[2 * ne2 + 0], pa, t4 + 0);
                mma_f16(o[2 * ne2 + 1], pa, t4 + 2);
            }
        }

        // epilogue: residual add, guarded stores
        int r0 = mt * 16 + (lane >> 2);
        int cb = (lane & 3) * 2;
        if (r0 < SEQL) {
            size_t base = ((size_t)b * SEQL + r0) * HD + h * DH;
#pragma unroll
            for (int ne = 0; ne < 8; ne++) {
                int n = ne * 8 + cb;
                float2 t = *(const float2*)(g_tokens + base + n);
                float2 ov = {t.x + o[ne][0], t.y + o[ne][1]};
                *(float2*)(out + base + n) = ov;
            }
        }
        if (r0 + 8 < SEQL) {
            size_t base = ((size_t)b * SEQL + r0 + 8) * HD + h * DH;
#pragma unroll
            for (int ne = 0; ne < 8; ne++) {
                int n = ne * 8 + cb;
                float2 t = *(const float2*)(g_tokens + base + n);
                float2 ov = {t.x + o[ne][2], t.y + o[ne][3]};
                *(float2*)(out + base + n) = ov;
            }
        }
    }
}

// ---------------- launcher ----------------
extern "C" void kernel_launch(void* const* d_in, const int* in_sizes, int n_in,
                              void* d_out, int out_size) {
    const float* images = (const float*)d_in[0];
    const float* W_map  = (const float*)d_in[1];
    const float* b_map  = (const float*)d_in[2];
    const float* cls    = (const float*)d_in[3];
    const float* ln_w   = (const float*)d_in[4];
    const float* ln_b   = (const float*)d_in[5];
    const float* Wq     = (const float*)d_in[6];
    const float* bq     = (const float*)d_in[7];
    const float* Wk     = (const float*)d_in[8];
    const float* bk     = (const float*)d_in[9];
    const float* Wv     = (const float*)d_in[10];
    const float* bv     = (const float*)d_in[11];
    float* out = (float*)d_out;

    cudaFuncSetAttribute(gemm_tokens_mma, cudaFuncAttributeMaxDynamicSharedMemorySize, G_SMEM);
    cudaFuncSetAttribute(qkv_attn_fused, cudaFuncAttributeMaxDynamicSharedMemorySize, FUSED_SMEM);

    pos_kernel<<<(SEQL * HD + 255) / 256, 256>>>();
    cls_kernel<<<NB, 256>>>(cls);
    cvt_kernel<<<4736, 256>>>(images, W_map);
    gemm_tokens_mma<<<dim3(HD / 128, (NB * NPAT) / 128), 256, G_SMEM>>>(b_map);
    finalize_kernel<<<1, 128>>>();
    qkv_attn_fused<<<NB * NH, NTH, FUSED_SMEM>>>(ln_w, ln_b, Wq, bq, Wk, bk, Wv, bv, out);
}

// round 16
// speedup vs baseline: 1.0100x; 1.0100x over previous
#include <cuda_runtime.h>
#include <cuda_fp16.h>
#include <math.h>
#include <stdint.h>

#define NB   128
#define SEQL 197
#define NPAT 196
#define HD   768
#define NH   12
#define DH   64
#define LN_EPS 1e-5f
#define NA   (NB * NPAT * HD)   // 19267584 image elems
#define NW   (HD * HD)

// ---------------- scratch (static device globals; no allocs) ----------------
static __device__ float g_tokens[NB * SEQL * HD];          // 77.4 MB
static __device__ float g_pos[SEQL * HD];
static __device__ float g_mean[NB];
static __device__ float g_rstd[NB];
static __device__ float g_sum[NB];
static __device__ float g_sumsq[NB];
static __device__ __half g_Ah[NA];                          // fp16 images
static __device__ __half g_Wh[NW];                          // fp16 W_map

// ================= helpers =================
__device__ __forceinline__ uint32_t smem_u32(const void* p) {
    uint32_t a;
    asm("{ .reg .u64 t; cvta.to.shared.u64 t, %1; cvt.u32.u64 %0, t; }" : "=r"(a) : "l"(p));
    return a;
}
#define LDSM4(r, addr) \
    asm volatile("ldmatrix.sync.aligned.m8n8.x4.shared.b16 {%0,%1,%2,%3}, [%4];" \
        : "=r"((r)[0]), "=r"((r)[1]), "=r"((r)[2]), "=r"((r)[3]) : "r"(addr))

__device__ __forceinline__ void mma_f16(float* c, const uint32_t* a, const uint32_t* b) {
    asm volatile("mma.sync.aligned.m16n8k16.row.col.f32.f16.f16.f32 "
        "{%0,%1,%2,%3}, {%4,%5,%6,%7}, {%8,%9}, {%0,%1,%2,%3};"
        : "+f"(c[0]), "+f"(c[1]), "+f"(c[2]), "+f"(c[3])
        : "r"(a[0]), "r"(a[1]), "r"(a[2]), "r"(a[3]), "r"(b[0]), "r"(b[1]));
}

__device__ __forceinline__ uint32_t pack_h_f(float x, float y) {
    __half2 t = __floats2half2_rn(x, y);
    return *(uint32_t*)&t;
}
__device__ __forceinline__ uint2 cvt_f4(float4 v) {
    uint2 r;
    r.x = pack_h_f(v.x, v.y);
    r.y = pack_h_f(v.z, v.w);
    return r;
}
__device__ __forceinline__ uint32_t ex2_h2(uint32_t y) {
    uint32_t r;
    asm("ex2.approx.f16x2 %0, %1;" : "=r"(r) : "r"(y));
    return r;
}
__device__ __forceinline__ uint32_t hmul2_u(uint32_t a, uint32_t b) {
    __half2 t = __hmul2(*(__half2*)&a, *(__half2*)&b);
    return *(uint32_t*)&t;
}

// ---------------- positional embeddings (+ zero stat accumulators) ----------------
__global__ void pos_kernel() {
    int idx = blockIdx.x * blockDim.x + threadIdx.x;
    if (idx < NB) { g_sum[idx] = 0.f; g_sumsq[idx] = 0.f; }
    if (idx >= SEQL * HD) return;
    int i = idx / HD, j = idx % HD;
    float jf = (float)(j & ~1);
    float denom = powf(10000.0f, jf / (float)HD);
    float arg = (float)i / denom;
    g_pos[idx] = (j & 1) ? cosf(arg) : sinf(arg);
}

// ---------------- class token row (+ stats contribution) ----------------
__global__ __launch_bounds__(256) void cls_kernel(const float* __restrict__ cls) {
    int b = blockIdx.x;
    float s = 0.f, q = 0.f;
    for (int j = threadIdx.x; j < HD; j += 256) {
        float v = cls[j] + g_pos[j];
        g_tokens[(size_t)b * SEQL * HD + j] = v;
        s += v; q += v * v;
    }
#pragma unroll
    for (int o = 16; o; o >>= 1) {
        s += __shfl_xor_sync(0xffffffffu, s, o);
        q += __shfl_xor_sync(0xffffffffu, q, o);
    }
    __shared__ float sh[16];
    int w = threadIdx.x >> 5, l = threadIdx.x & 31;
    if (!l) { sh[w] = s; sh[8 + w] = q; }
    __syncthreads();
    if (threadIdx.x == 0) {
        float S = 0.f, Q = 0.f;
        for (int i = 0; i < 8; i++) { S += sh[i]; Q += sh[8 + i]; }
        atomicAdd(&g_sum[b], S);
        atomicAdd(&g_sumsq[b], Q);
    }
}

// ---------------- fp32 -> fp16 pre-convert (images + W_map) ----------------
__global__ __launch_bounds__(256) void cvt_kernel(const float* __restrict__ A,
                                                  const float* __restrict__ Wm) {
    const int stride = gridDim.x * blockDim.x;
    const int tot4 = (NA + NW) / 4;
    for (int i = blockIdx.x * blockDim.x + threadIdx.x; i < tot4; i += stride) {
        if (i < NA / 4) {
            float4 v = ((const float4*)A)[i];
            *(uint2*)&g_Ah[(size_t)i * 4] = cvt_f4(v);
        } else {
            int j = i - NA / 4;
            float4 v = ((const float4*)Wm)[j];
            *(uint2*)&g_Wh[(size_t)j * 4] = cvt_f4(v);
        }
    }
}

// ---------------- token projection GEMM: fp16 mma + cp.async, 1 sync/iter -----
// C[m,n] = sum_k A[m,k]*W[n,k]; M=25088, N=768, K=768.
// CTA tile 128x128, BK=64, 8 warps (4m x 2n), warp tile 32x64. 2 CTA/SM.
// (inner loop = R13 form: known 128-reg no-spill configuration)
#define KS 72
#define GST (256 * KS)            // halves per stage
#define G_SMEM (3 * GST * 2)      // 110592 bytes

#define GEMM_ISSUE(ktile) do { \
    __half* st_ = sm + ((ktile) % 3) * GST; \
    const int kb_ = (ktile) * 64; \
    _Pragma("unroll") \
    for (int it = 0; it < 8; it++) { \
        int ch = it * 256 + tid; \
        int row = ch >> 3, c8 = ch & 7; \
        const __half* src = (row < 128) \
            ? (g_Ah + (size_t)(m0 + row) * HD + kb_ + c8 * 8) \
            : (g_Wh + (size_t)(n0 + row - 128) * HD + kb_ + c8 * 8); \
        uint32_t dst = smem_u32(&st_[row * KS + c8 * 8]); \
        asm volatile("cp.async.cg.shared.global [%0], [%1], 16;" :: "r"(dst), "l"(src)); \
    } \
} while (0)
#define CP_COMMIT() asm volatile("cp.async.commit_group;" ::: "memory")
#define CP_WAIT1()  asm volatile("cp.async.wait_group 1;" ::: "memory")

__global__ __launch_bounds__(256, 2) void gemm_tokens_mma(const float* __restrict__ bias) {
    extern __shared__ char smc[];
    __half* sm = (__half*)smc;
    const int tid  = threadIdx.x;
    const int lane = tid & 31, wid = tid >> 5;
    const int wm = wid & 3, wn = wid >> 2;
    const int seg = lane >> 3;
    const int n0 = blockIdx.x * 128;
    const int m0 = blockIdx.y * 128;

    float c[2][8][4] = {};

    GEMM_ISSUE(0); CP_COMMIT();
    GEMM_ISSUE(1); CP_COMMIT();

    for (int kt = 0; kt < 12; kt++) {
        CP_WAIT1();              // tile kt complete (only kt+1 may remain in flight)
        __syncthreads();         // all warps past compute of kt-1 -> slot (kt+2)%3 free
        if (kt + 2 < 12) GEMM_ISSUE(kt + 2);
        CP_COMMIT();
        __half* st = sm + (kt % 3) * GST;
#pragma unroll
        for (int ks = 0; ks < 4; ks++) {
            const int k0 = ks * 16;
            uint32_t a[2][4];
#pragma unroll
            for (int mf = 0; mf < 2; mf++) {
                int r = wm * 32 + mf * 16 + (lane & 15);
                int ko = k0 + (lane >> 4) * 8;
                LDSM4(a[mf], smem_u32(&st[r * KS + ko]));
            }
#pragma unroll
            for (int nf2 = 0; nf2 < 4; nf2++) {
                int r = wn * 64 + nf2 * 16 + (seg >> 1) * 8 + (lane & 7);
                int ko = k0 + (seg & 1) * 8;
                uint32_t bfr[4];
                LDSM4(bfr, smem_u32(&st[128 * KS + r * KS + ko]));
#pragma unroll
                for (int mf = 0; mf < 2; mf++) {
                    mma_f16(c[mf][nf2 * 2 + 0], a[mf], bfr + 0);
                    mma_f16(c[mf][nf2 * 2 + 1], a[mf], bfr + 2);
                }
            }
        }
    }

    // epilogue: + bias + pos, scatter; accumulate per-sample stats
    float ssum[2] = {0.f, 0.f}, ssq[2] = {0.f, 0.f};
    const int bbase = m0 / NPAT;
    const bool has2 = ((m0 + 127) / NPAT) != bbase;
#pragma unroll
    for (int mf = 0; mf < 2; mf++) {
#pragma unroll
        for (int half = 0; half < 2; half++) {
            int mg = m0 + wm * 32 + mf * 16 + (lane >> 2) + half * 8;
            int b = mg / NPAT, p = mg % NPAT;
            int slot = b - bbase;
            float* orow = g_tokens + ((size_t)b * SEQL + p + 1) * HD;
            const float* prow = g_pos + (size_t)(p + 1) * HD;
            float ls = 0.f, lq = 0.f;
#pragma unroll
            for (int nf = 0; nf < 8; nf++) {
                int col = n0 + wn * 64 + nf * 8 + (lane & 3) * 2;
                float2 o;
                o.x = c[mf][nf][half * 2 + 0] + bias[col] + prow[col];
                o.y = c[mf][nf][half * 2 + 1] + bias[col + 1] + prow[col + 1];
                *(float2*)(orow + col) = o;
                ls += o.x + o.y;
                lq += o.x * o.x + o.y * o.y;
            }
            ssum[slot] += ls;
            ssq[slot] += lq;
        }
    }
#pragma unroll
    for (int o = 16; o; o >>= 1) {
        ssum[0] += __shfl_xor_sync(0xffffffffu, ssum[0], o);
        ssq[0]  += __shfl_xor_sync(0xffffffffu, ssq[0], o);
        ssum[1] += __shfl_xor_sync(0xffffffffu, ssum[1], o);
        ssq[1]  += __shfl_xor_sync(0xffffffffu, ssq[1], o);
    }
    if (lane == 0) {
        atomicAdd(&g_sum[bbase], ssum[0]);
        atomicAdd(&g_sumsq[bbase], ssq[0]);
        if (has2) {
            atomicAdd(&g_sum[bbase + 1], ssum[1]);
            atomicAdd(&g_sumsq[bbase + 1], ssq[1]);
        }
    }
}

// ---------------- finalize LN stats ----------------
__global__ void finalize_kernel() {
    int b = threadIdx.x;
    if (b < NB) {
        const float n = (float)(SEQL * HD);
        float mean = g_sum[b] / n;
        float var  = g_sumsq[b] / n - mean * mean;
        g_mean[b] = mean;
        g_rstd[b] = rsqrtf(var + LN_EPS);
    }
}

// ---------------- fused QKV + attention: 416 threads = 13 warps ----------------
// (R13 form: Q staged through smem; A-frags hoisted in phase 1)
#define NTH  416
#define SEQP 208
#define QKS  72
#define VTS  216
#define FX  0
#define FW  (SEQP * QKS)
#define FK  (SEQP * QKS + 192 * QKS)
#define FQ  (FK + SEQP * QKS)
#define FVT (FQ + SEQP * QKS)
#define FUSED_SMEM ((FVT + 64 * VTS) * 2)

__global__ void __launch_bounds__(NTH, 1) qkv_attn_fused(
    const float* __restrict__ lnw, const float* __restrict__ lnb,
    const float* __restrict__ Wq, const float* __restrict__ bq,
    const float* __restrict__ Wk, const float* __restrict__ bk,
    const float* __restrict__ Wv, const float* __restrict__ bv,
    float* __restrict__ out) {
    extern __shared__ __half fsm[];
    const int tid = threadIdx.x, lane = tid & 31, w = tid >> 5;
    const int seg = lane >> 3;
    const int bh = blockIdx.x, b = bh / NH, h = bh % NH;
    const float mean = g_mean[b], rstd = g_rstd[b];
    const float* tb = g_tokens + (size_t)b * SEQL * HD + h * DH;

    // ---- phase 0: stage X normalized (fp16) and W (fp16) ----
    for (int idx = tid; idx < SEQP * 16; idx += NTH) {
        int s = idx >> 4, d4 = (idx & 15) * 4;
        float4 x = {0.f, 0.f, 0.f, 0.f};
        if (s < SEQL) {
            float4 tv = *(const float4*)(tb + (size_t)s * HD + d4);
            float4 wv = *(const float4*)(lnw + (size_t)s * HD + h * DH + d4);
            float4 bb = *(const float4*)(lnb + (size_t)s * HD + h * DH + d4);
            x.x = (tv.x - mean) * rstd * wv.x + bb.x;
            x.y = (tv.y - mean) * rstd * wv.y + bb.y;
            x.z = (tv.z - mean) * rstd * wv.z + bb.z;
            x.w = (tv.w - mean) * rstd * wv.w + bb.w;
        }
        *(uint2*)&fsm[FX + s * QKS + d4] = cvt_f4(x);
    }
    for (int idx = tid; idx < 3 * 64 * 16; idx += NTH) {
        int m = idx >> 10, rem = idx & 1023;
        int e = rem >> 4, d4 = (rem & 15) * 4;
        const float* Wsrc = (m == 0 ? Wq : (m == 1 ? Wk : Wv)) + (size_t)h * DH * DH;
        float4 v = *(const float4*)(Wsrc + e * DH + d4);
        *(uint2*)&fsm[FW + (m * 64 + e) * QKS + d4] = cvt_f4(v);
    }
    __syncthreads();

    // ---- phase 1: warp w does q/k/v for tile w (A-frags hoisted) ----
    {
        const int mt = w;
        uint32_t af[4][4];
#pragma unroll
        for (int ks = 0; ks < 4; ks++) {
            int r = mt * 16 + (lane & 15);
            int ko = ks * 16 + (lane >> 4) * 8;
            LDSM4(af[ks], smem_u32(&fsm[FX + r * QKS + ko]));
        }
#pragma unroll
        for (int m = 0; m < 3; m++) {
            float c[8][4] = {};
#pragma unroll
            for (int ks = 0; ks < 4; ks++) {
                const int k0 = ks * 16;
#pragma unroll
                for (int nf2 = 0; nf2 < 4; nf2++) {
                    int r = m * 64 + nf2 * 16 + (seg >> 1) * 8 + (lane & 7);
                    int ko = k0 + (seg & 1) * 8;
                    uint32_t bfr[4];
                    LDSM4(bfr, smem_u32(&fsm[FW + r * QKS + ko]));
                    mma_f16(c[nf2 * 2 + 0], af[ks], bfr + 0);
                    mma_f16(c[nf2 * 2 + 1], af[ks], bfr + 2);
                }
            }
            const float* bias = (m == 0 ? bq : (m == 1 ? bk : bv)) + h * DH;
            int r0 = mt * 16 + (lane >> 2);
#pragma unroll
            for (int half = 0; half < 2; half++) {
                int r = r0 + half * 8;   // < 208; padded rows hold bias (inert)
#pragma unroll
                for (int nf = 0; nf < 8; nf++) {
                    int e = nf * 8 + (lane & 3) * 2;
                    float v0 = c[nf][half * 2 + 0] + bias[e];
                    float v1 = c[nf][half * 2 + 1] + bias[e + 1];
                    if (m == 0) {
                        *(uint32_t*)&fsm[FQ + r * QKS + e] = pack_h_f(v0 * 0.125f, v1 * 0.125f);
                    } else if (m == 1) {
                        *(uint32_t*)&fsm[FK + r * QKS + e] = pack_h_f(v0, v1);
                    } else {
                        fsm[FVT + e * VTS + r] = __float2half_rn(v0);
                        fsm[FVT + (e + 1) * VTS + r] = __float2half_rn(v1);
                    }
                }
            }
        }
    }
    __syncthreads();

    // ---- phase 2: attention, one m-tile per warp ----
    {
        const int mt = w;
        float c[26][4];
#pragma unroll
        for (int nf = 0; nf < 26; nf++)
            c[nf][0] = c[nf][1] = c[nf][2] = c[nf][3] = 0.f;

        // S = Qs * K^T
#pragma unroll
        for (int ksx = 0; ksx < 4; ksx++) {
            uint32_t a[4];
            {
                int r = mt * 16 + (lane & 15);
                int co = ksx * 16 + (lane >> 4) * 8;
                LDSM4(a, smem_u32(&fsm[FQ + r * QKS + co]));
            }
#pragma unroll
            for (int nf2 = 0; nf2 < 13; nf2++) {
                int r = nf2 * 16 + (seg >> 1) * 8 + (lane & 7);
                int co = ksx * 16 + (seg & 1) * 8;
                uint32_t t4[4];
                LDSM4(t4, smem_u32(&fsm[FK + r * QKS + co]));
                mma_f16(c[2 * nf2 + 0], a, t4 + 0);
                mma_f16(c[2 * nf2 + 1], a, t4 + 2);
            }
        }

        // mask padded columns (cols >= 197)
        {
            int cb = (lane & 3) * 2;
            if (192 + cb >= SEQL) { c[24][0] = -1e30f; c[24][2] = -1e30f; }
            if (193 + cb >= SEQL) { c[24][1] = -1e30f; c[24][3] = -1e30f; }
            c[25][0] = c[25][1] = c[25][2] = c[25][3] = -1e30f;
        }

        // softmax: row max, then P = 2^(L2E*(s - mx)) via ex2.approx.f16x2
        float mx0 = -1e30f, mx1 = -1e30f;
#pragma unroll
        for (int nf = 0; nf < 26; nf++) {
            mx0 = fmaxf(mx0, fmaxf(c[nf][0], c[nf][1]));
            mx1 = fmaxf(mx1, fmaxf(c[nf][2], c[nf][3]));
        }
        mx0 = fmaxf(mx0, __shfl_xor_sync(0xffffffffu, mx0, 1));
        mx0 = fmaxf(mx0, __shfl_xor_sync(0xffffffffu, mx0, 2));
        mx1 = fmaxf(mx1, __shfl_xor_sync(0xffffffffu, mx1, 1));
        mx1 = fmaxf(mx1, __shfl_xor_sync(0xffffffffu, mx1, 2));

        const float L2E = 1.4426950408889634f;
        const float b0 = mx0 * L2E, b1 = mx1 * L2E;
        uint32_t ph[26][2];
        float s0 = 0.f, s1 = 0.f;
#pragma unroll
        for (int nf = 0; nf < 26; nf++) {
            uint32_t y0 = pack_h_f(fmaf(c[nf][0], L2E, -b0), fmaf(c[nf][1], L2E, -b0));
            uint32_t y1 = pack_h_f(fmaf(c[nf][2], L2E, -b1), fmaf(c[nf][3], L2E, -b1));
            ph[nf][0] = ex2_h2(y0);
            ph[nf][1] = ex2_h2(y1);
            float2 f0 = __half22float2(*(__half2*)&ph[nf][0]);
            float2 f1 = __half22float2(*(__half2*)&ph[nf][1]);
            s0 += f0.x + f0.y;
            s1 += f1.x + f1.y;
        }
        s0 += __shfl_xor_sync(0xffffffffu, s0, 1);
        s0 += __shfl_xor_sync(0xffffffffu, s0, 2);
        s1 += __shfl_xor_sync(0xffffffffu, s1, 1);
        s1 += __shfl_xor_sync(0xffffffffu, s1, 2);
        float inv0 = 1.0f / s0, inv1 = 1.0f / s1;
        uint32_t ih0 = pack_h_f(inv0, inv0);
        uint32_t ih1 = pack_h_f(inv1, inv1);

        // O = P * V^T
        float o[8][4];
#pragma unroll
        for (int ne = 0; ne < 8; ne++)
            o[ne][0] = o[ne][1] = o[ne][2] = o[ne][3] = 0.f;

#pragma unroll
        for (int kt = 0; kt < 13; kt++) {
            uint32_t pa[4];
            pa[0] = hmul2_u(ph[2 * kt][0], ih0);
            pa[1] = hmul2_u(ph[2 * kt][1], ih1);
            pa[2] = hmul2_u(ph[2 * kt + 1][0], ih0);
            pa[3] = hmul2_u(ph[2 * kt + 1][1], ih1);
#pragma unroll
            for (int ne2 = 0; ne2 < 4; ne2++) {
                int r = ne2 * 16 + (seg >> 1) * 8 + (lane & 7);
                int co = kt * 16 + (seg & 1) * 8;
                uint32_t t4[4];
                LDSM4(t4, smem_u32(&fsm[FVT + r * VTS + co]));
                mma_f16(o[2 * ne2 + 0], pa, t4 + 0);
                mma_f16(o[2 * ne2 + 1], pa, t4 + 2);
            }
        }

        // epilogue: residual add, guarded stores
        int r0 = mt * 16 + (lane >> 2);
        int cb = (lane & 3) * 2;
        if (r0 < SEQL) {
            size_t base = ((size_t)b * SEQL + r0) * HD + h * DH;
#pragma unroll
            for (int ne = 0; ne < 8; ne++) {
                int n = ne * 8 + cb;
                float2 t = *(const float2*)(g_tokens + base + n);
                float2 ov = {t.x + o[ne][0], t.y + o[ne][1]};
                *(float2*)(out + base + n) = ov;
            }
        }
        if (r0 + 8 < SEQL) {
            size_t base = ((size_t)b * SEQL + r0 + 8) * HD + h * DH;
#pragma unroll
            for (int ne = 0; ne < 8; ne++) {
                int n = ne * 8 + cb;
                float2 t = *(const float2*)(g_tokens + base + n);
                float2 ov = {t.x + o[ne][2], t.y + o[ne][3]};
                *(float2*)(out + base + n) = ov;
            }
        }
    }
}

// ---------------- launcher ----------------
extern "C" void kernel_launch(void* const* d_in, const int* in_sizes, int n_in,
                              void* d_out, int out_size) {
    const float* images = (const float*)d_in[0];
    const float* W_map  = (const float*)d_in[1];
    const float* b_map  = (const float*)d_in[2];
    const float* cls    = (const float*)d_in[3];
    const float* ln_w   = (const float*)d_in[4];
    const float* ln_b   = (const float*)d_in[5];
    const float* Wq     = (const float*)d_in[6];
    const float* bq     = (const float*)d_in[7];
    const float* Wk     = (const float*)d_in[8];
    const float* bk     = (const float*)d_in[9];
    const float* Wv     = (const float*)d_in[10];
    const float* bv     = (const float*)d_in[11];
    float* out = (float*)d_out;

    cudaFuncSetAttribute(gemm_tokens_mma, cudaFuncAttributeMaxDynamicSharedMemorySize, G_SMEM);
    cudaFuncSetAttribute(qkv_attn_fused, cudaFuncAttributeMaxDynamicSharedMemorySize, FUSED_SMEM);

    pos_kernel<<<(SEQL * HD + 255) / 256, 256>>>();
    cls_kernel<<<NB, 256>>>(cls);
    cvt_kernel<<<4736, 256>>>(images, W_map);
    gemm_tokens_mma<<<dim3(HD / 128, (NB * NPAT) / 128), 256, G_SMEM>>>(b_map);
    finalize_kernel<<<1, 128>>>();
    qkv_attn_fused<<<NB * NH, NTH, FUSED_SMEM>>>(ln_w, ln_b, Wq, bq, Wk, bk, Wv, bv, out);
}

// round 17
// speedup vs baseline: 1.0306x; 1.0204x over previous
#include <cuda_runtime.h>
#include <cuda_fp16.h>
#include <math.h>
#include <stdint.h>

#define NB   128
#define SEQL 197
#define NPAT 196
#define HD   768
#define NH   12
#define DH   64
#define LN_EPS 1e-5f
#define NA   (NB * NPAT * HD)   // 19267584 image elems
#define NW   (HD * HD)

// ---------------- scratch (static device globals; no allocs) ----------------
static __device__ float g_tokens[NB * SEQL * HD];          // 77.4 MB
static __device__ float g_pos[SEQL * HD];
static __device__ float g_mean[NB];
static __device__ float g_rstd[NB];
static __device__ __half g_Ah[NA];                          // fp16 images
static __device__ __half g_Wh[NW];                          // fp16 W_map

// ================= helpers =================
__device__ __forceinline__ uint32_t smem_u32(const void* p) {
    uint32_t a;
    asm("{ .reg .u64 t; cvta.to.shared.u64 t, %1; cvt.u32.u64 %0, t; }" : "=r"(a) : "l"(p));
    return a;
}
#define LDSM4(r, addr) \
    asm volatile("ldmatrix.sync.aligned.m8n8.x4.shared.b16 {%0,%1,%2,%3}, [%4];" \
        : "=r"((r)[0]), "=r"((r)[1]), "=r"((r)[2]), "=r"((r)[3]) : "r"(addr))

__device__ __forceinline__ void mma_f16(float* c, const uint32_t* a, const uint32_t* b) {
    asm volatile("mma.sync.aligned.m16n8k16.row.col.f32.f16.f16.f32 "
        "{%0,%1,%2,%3}, {%4,%5,%6,%7}, {%8,%9}, {%0,%1,%2,%3};"
        : "+f"(c[0]), "+f"(c[1]), "+f"(c[2]), "+f"(c[3])
        : "r"(a[0]), "r"(a[1]), "r"(a[2]), "r"(a[3]), "r"(b[0]), "r"(b[1]));
}

__device__ __forceinline__ uint32_t pack_h_f(float x, float y) {
    __half2 t = __floats2half2_rn(x, y);
    return *(uint32_t*)&t;
}
__device__ __forceinline__ uint2 cvt_f4(float4 v) {
    uint2 r;
    r.x = pack_h_f(v.x, v.y);
    r.y = pack_h_f(v.z, v.w);
    return r;
}
__device__ __forceinline__ uint32_t ex2_h2(uint32_t y) {
    uint32_t r;
    asm("ex2.approx.f16x2 %0, %1;" : "=r"(r) : "r"(y));
    return r;
}
__device__ __forceinline__ uint32_t hmul2_u(uint32_t a, uint32_t b) {
    __half2 t = __hmul2(*(__half2*)&a, *(__half2*)&b);
    return *(uint32_t*)&t;
}

// ---------------- positional embeddings ----------------
__global__ void pos_kernel() {
    int idx = blockIdx.x * blockDim.x + threadIdx.x;
    if (idx >= SEQL * HD) return;
    int i = idx / HD, j = idx % HD;
    float jf = (float)(j & ~1);
    float denom = powf(10000.0f, jf / (float)HD);
    float arg = (float)i / denom;
    g_pos[idx] = (j & 1) ? cosf(arg) : sinf(arg);
}

// ---------------- class token row ----------------
__global__ void cls_kernel(const float* __restrict__ cls) {
    int b = blockIdx.x;
    for (int j = threadIdx.x; j < HD; j += blockDim.x)
        g_tokens[(size_t)b * SEQL * HD + j] = cls[j] + g_pos[j];
}

// ---------------- fp32 -> fp16 pre-convert (images + W_map) ----------------
__global__ __launch_bounds__(256) void cvt_kernel(const float* __restrict__ A,
                                                  const float* __restrict__ Wm) {
    const int stride = gridDim.x * blockDim.x;
    const int tot4 = (NA + NW) / 4;
    for (int i = blockIdx.x * blockDim.x + threadIdx.x; i < tot4; i += stride) {
        if (i < NA / 4) {
            float4 v = ((const float4*)A)[i];
            *(uint2*)&g_Ah[(size_t)i * 4] = cvt_f4(v);
        } else {
            int j = i - NA / 4;
            float4 v = ((const float4*)Wm)[j];
            *(uint2*)&g_Wh[(size_t)j * 4] = cvt_f4(v);
        }
    }
}

// ---------------- token projection GEMM: fp16 mma + cp.async, 1 sync/iter -----
// (exact R13 configuration: 115.9us measured, regs=128, no spills)
#define KS 72
#define GST (256 * KS)
#define G_SMEM (3 * GST * 2)

#define GEMM_ISSUE(ktile) do { \
    __half* st_ = sm + ((ktile) % 3) * GST; \
    const int kb_ = (ktile) * 64; \
    _Pragma("unroll") \
    for (int it = 0; it < 8; it++) { \
        int ch = it * 256 + tid; \
        int row = ch >> 3, c8 = ch & 7; \
        const __half* src = (row < 128) \
            ? (g_Ah + (size_t)(m0 + row) * HD + kb_ + c8 * 8) \
            : (g_Wh + (size_t)(n0 + row - 128) * HD + kb_ + c8 * 8); \
        uint32_t dst = smem_u32(&st_[row * KS + c8 * 8]); \
        asm volatile("cp.async.cg.shared.global [%0], [%1], 16;" :: "r"(dst), "l"(src)); \
    } \
} while (0)
#define CP_COMMIT() asm volatile("cp.async.commit_group;" ::: "memory")
#define CP_WAIT1()  asm volatile("cp.async.wait_group 1;" ::: "memory")

__global__ __launch_bounds__(256, 2) void gemm_tokens_mma(const float* __restrict__ bias) {
    extern __shared__ char smc[];
    __half* sm = (__half*)smc;
    const int tid  = threadIdx.x;
    const int lane = tid & 31, wid = tid >> 5;
    const int wm = wid & 3, wn = wid >> 2;
    const int seg = lane >> 3;
    const int n0 = blockIdx.x * 128;
    const int m0 = blockIdx.y * 128;

    float c[2][8][4] = {};

    GEMM_ISSUE(0); CP_COMMIT();
    GEMM_ISSUE(1); CP_COMMIT();

    for (int kt = 0; kt < 12; kt++) {
        CP_WAIT1();
        __syncthreads();
        if (kt + 2 < 12) GEMM_ISSUE(kt + 2);
        CP_COMMIT();
        __half* st = sm + (kt % 3) * GST;
#pragma unroll
        for (int ks = 0; ks < 4; ks++) {
            const int k0 = ks * 16;
            uint32_t a[2][4];
#pragma unroll
            for (int mf = 0; mf < 2; mf++) {
                int r = wm * 32 + mf * 16 + (lane & 15);
                int ko = k0 + (lane >> 4) * 8;
                LDSM4(a[mf], smem_u32(&st[r * KS + ko]));
            }
#pragma unroll
            for (int nf2 = 0; nf2 < 4; nf2++) {
                int r = wn * 64 + nf2 * 16 + (seg >> 1) * 8 + (lane & 7);
                int ko = k0 + (seg & 1) * 8;
                uint32_t bfr[4];
                LDSM4(bfr, smem_u32(&st[128 * KS + r * KS + ko]));
#pragma unroll
                for (int mf = 0; mf < 2; mf++) {
                    mma_f16(c[mf][nf2 * 2 + 0], a[mf], bfr + 0);
                    mma_f16(c[mf][nf2 * 2 + 1], a[mf], bfr + 2);
                }
            }
        }
    }

#pragma unroll
    for (int mf = 0; mf < 2; mf++) {
#pragma unroll
        for (int half = 0; half < 2; half++) {
            int mg = m0 + wm * 32 + mf * 16 + (lane >> 2) + half * 8;
            int b = mg / NPAT, p = mg % NPAT;
            float* orow = g_tokens + ((size_t)b * SEQL + p + 1) * HD;
            const float* prow = g_pos + (size_t)(p + 1) * HD;
#pragma unroll
            for (int nf = 0; nf < 8; nf++) {
                int col = n0 + wn * 64 + nf * 8 + (lane & 3) * 2;
                float2 o;
                o.x = c[mf][nf][half * 2 + 0] + bias[col] + prow[col];
                o.y = c[mf][nf][half * 2 + 1] + bias[col + 1] + prow[col + 1];
                *(float2*)(orow + col) = o;
            }
        }
    }
}

// ---------------- per-sample LN stats ----------------
__global__ __launch_bounds__(1024) void stats_kernel() {
    int b = blockIdx.x;
    const float4* base = (const float4*)(g_tokens + (size_t)b * SEQL * HD);
    const int n4 = SEQL * HD / 4;
    float s = 0.f, sq = 0.f;
    for (int i = threadIdx.x; i < n4; i += 1024) {
        float4 v = base[i];
        s  += v.x + v.y + v.z + v.w;
        sq += v.x * v.x + v.y * v.y + v.z * v.z + v.w * v.w;
    }
    __shared__ float sh[64];
#pragma unroll
    for (int o = 16; o; o >>= 1) {
        s  += __shfl_xor_sync(0xffffffffu, s, o);
        sq += __shfl_xor_sync(0xffffffffu, sq, o);
    }
    int w = threadIdx.x >> 5, l = threadIdx.x & 31;
    if (!l) { sh[w] = s; sh[32 + w] = sq; }
    __syncthreads();
    if (threadIdx.x == 0) {
        float S = 0.f, Q = 0.f;
        for (int i = 0; i < 32; i++) { S += sh[i]; Q += sh[32 + i]; }
        const float n = (float)(SEQL * HD);
        float mean = S / n;
        float var  = Q / n - mean * mean;
        g_mean[b] = mean;
        g_rstd[b] = rsqrtf(var + LN_EPS);
    }
}

// ---------------- fused QKV + attention: 416 threads = 13 warps ----------------
// R13 base + depth-1 double-buffered K/Vt fragment loads in phase 2.
#define NTH  416
#define SEQP 208
#define QKS  72
#define VTS  216
#define FX  0
#define FW  (SEQP * QKS)
#define FK  (SEQP * QKS + 192 * QKS)
#define FQ  (FK + SEQP * QKS)
#define FVT (FQ + SEQP * QKS)
#define FUSED_SMEM ((FVT + 64 * VTS) * 2)

__global__ void __launch_bounds__(NTH, 1) qkv_attn_fused(
    const float* __restrict__ lnw, const float* __restrict__ lnb,
    const float* __restrict__ Wq, const float* __restrict__ bq,
    const float* __restrict__ Wk, const float* __restrict__ bk,
    const float* __restrict__ Wv, const float* __restrict__ bv,
    float* __restrict__ out) {
    extern __shared__ __half fsm[];
    const int tid = threadIdx.x, lane = tid & 31, w = tid >> 5;
    const int seg = lane >> 3;
    const int bh = blockIdx.x, b = bh / NH, h = bh % NH;
    const float mean = g_mean[b], rstd = g_rstd[b];
    const float* tb = g_tokens + (size_t)b * SEQL * HD + h * DH;

    // ---- phase 0: stage X normalized (fp16) and W (fp16) ----
    for (int idx = tid; idx < SEQP * 16; idx += NTH) {
        int s = idx >> 4, d4 = (idx & 15) * 4;
        float4 x = {0.f, 0.f, 0.f, 0.f};
        if (s < SEQL) {
            float4 tv = *(const float4*)(tb + (size_t)s * HD + d4);
            float4 wv = *(const float4*)(lnw + (size_t)s * HD + h * DH + d4);
            float4 bb = *(const float4*)(lnb + (size_t)s * HD + h * DH + d4);
            x.x = (tv.x - mean) * rstd * wv.x + bb.x;
            x.y = (tv.y - mean) * rstd * wv.y + bb.y;
            x.z = (tv.z - mean) * rstd * wv.z + bb.z;
            x.w = (tv.w - mean) * rstd * wv.w + bb.w;
        }
        *(uint2*)&fsm[FX + s * QKS + d4] = cvt_f4(x);
    }
    for (int idx = tid; idx < 3 * 64 * 16; idx += NTH) {
        int m = idx >> 10, rem = idx & 1023;
        int e = rem >> 4, d4 = (rem & 15) * 4;
        const float* Wsrc = (m == 0 ? Wq : (m == 1 ? Wk : Wv)) + (size_t)h * DH * DH;
        float4 v = *(const float4*)(Wsrc + e * DH + d4);
        *(uint2*)&fsm[FW + (m * 64 + e) * QKS + d4] = cvt_f4(v);
    }
    __syncthreads();

    // ---- phase 1: warp w does q/k/v for tile w (A-frags hoisted) ----
    {
        const int mt = w;
        uint32_t af[4][4];
#pragma unroll
        for (int ks = 0; ks < 4; ks++) {
            int r = mt * 16 + (lane & 15);
            int ko = ks * 16 + (lane >> 4) * 8;
            LDSM4(af[ks], smem_u32(&fsm[FX + r * QKS + ko]));
        }
#pragma unroll
        for (int m = 0; m < 3; m++) {
            float c[8][4] = {};
#pragma unroll
            for (int ks = 0; ks < 4; ks++) {
                const int k0 = ks * 16;
#pragma unroll
                for (int nf2 = 0; nf2 < 4; nf2++) {
                    int r = m * 64 + nf2 * 16 + (seg >> 1) * 8 + (lane & 7);
                    int ko = k0 + (seg & 1) * 8;
                    uint32_t bfr[4];
                    LDSM4(bfr, smem_u32(&fsm[FW + r * QKS + ko]));
                    mma_f16(c[nf2 * 2 + 0], af[ks], bfr + 0);
                    mma_f16(c[nf2 * 2 + 1], af[ks], bfr + 2);
                }
            }
            const float* bias = (m == 0 ? bq : (m == 1 ? bk : bv)) + h * DH;
            int r0 = mt * 16 + (lane >> 2);
#pragma unroll
            for (int half = 0; half < 2; half++) {
                int r = r0 + half * 8;   // < 208; padded rows hold bias (inert)
#pragma unroll
                for (int nf = 0; nf < 8; nf++) {
                    int e = nf * 8 + (lane & 3) * 2;
                    float v0 = c[nf][half * 2 + 0] + bias[e];
                    float v1 = c[nf][half * 2 + 1] + bias[e + 1];
                    if (m == 0) {
                        *(uint32_t*)&fsm[FQ + r * QKS + e] = pack_h_f(v0 * 0.125f, v1 * 0.125f);
                    } else if (m == 1) {
                        *(uint32_t*)&fsm[FK + r * QKS + e] = pack_h_f(v0, v1);
                    } else {
                        fsm[FVT + e * VTS + r] = __float2half_rn(v0);
                        fsm[FVT + (e + 1) * VTS + r] = __float2half_rn(v1);
                    }
                }
            }
        }
    }
    __syncthreads();

    // ---- phase 2: attention, one m-tile per warp ----
    {
        const int mt = w;
        float c[26][4];
#pragma unroll
        for (int nf = 0; nf < 26; nf++)
            c[nf][0] = c[nf][1] = c[nf][2] = c[nf][3] = 0.f;

        // S = Qs * K^T  (double-buffered K fragments)
#pragma unroll
        for (int ksx = 0; ksx < 4; ksx++) {
            uint32_t a[4];
            {
                int r = mt * 16 + (lane & 15);
                int co = ksx * 16 + (lane >> 4) * 8;
                LDSM4(a, smem_u32(&fsm[FQ + r * QKS + co]));
            }
            const int co = ksx * 16 + (seg & 1) * 8;
            const int rb = (seg >> 1) * 8 + (lane & 7);
            uint32_t t4[2][4];
            LDSM4(t4[0], smem_u32(&fsm[FK + rb * QKS + co]));
#pragma unroll
            for (int nf2 = 0; nf2 < 13; nf2++) {
                if (nf2 < 12) {
                    int r = (nf2 + 1) * 16 + rb;
                    LDSM4(t4[(nf2 + 1) & 1], smem_u32(&fsm[FK + r * QKS + co]));
                }
                mma_f16(c[2 * nf2 + 0], a, t4[nf2 & 1] + 0);
                mma_f16(c[2 * nf2 + 1], a, t4[nf2 & 1] + 2);
            }
        }

        // mask padded columns (cols >= 197)
        {
            int cb = (lane & 3) * 2;
            if (192 + cb >= SEQL) { c[24][0] = -1e30f; c[24][2] = -1e30f; }
            if (193 + cb >= SEQL) { c[24][1] = -1e30f; c[24][3] = -1e30f; }
            c[25][0] = c[25][1] = c[25][2] = c[25][3] = -1e30f;
        }

        // softmax: row max, then P = 2^(L2E*(s - mx)) via ex2.approx.f16x2
        float mx0 = -1e30f, mx1 = -1e30f;
#pragma unroll
        for (int nf = 0; nf < 26; nf++) {
            mx0 = fmaxf(mx0, fmaxf(c[nf][0], c[nf][1]));
            mx1 = fmaxf(mx1, fmaxf(c[nf][2], c[nf][3]));
        }
        mx0 = fmaxf(mx0, __shfl_xor_sync(0xffffffffu, mx0, 1));
        mx0 = fmaxf(mx0, __shfl_xor_sync(0xffffffffu, mx0, 2));
        mx1 = fmaxf(mx1, __shfl_xor_sync(0xffffffffu, mx1, 1));
        mx1 = fmaxf(mx1, __shfl_xor_sync(0xffffffffu, mx1, 2));

        const float L2E = 1.4426950408889634f;
        const float b0 = mx0 * L2E, b1 = mx1 * L2E;
        uint32_t ph[26][2];
        float s0 = 0.f, s1 = 0.f;
#pragma unroll
        for (int nf = 0; nf < 26; nf++) {
            uint32_t y0 = pack_h_f(fmaf(c[nf][0], L2E, -b0), fmaf(c[nf][1], L2E, -b0));
            uint32_t y1 = pack_h_f(fmaf(c[nf][2], L2E, -b1), fmaf(c[nf][3], L2E, -b1));
            ph[nf][0] = ex2_h2(y0);
            ph[nf][1] = ex2_h2(y1);
            float2 f0 = __half22float2(*(__half2*)&ph[nf][0]);
            float2 f1 = __half22float2(*(__half2*)&ph[nf][1]);
            s0 += f0.x + f0.y;
            s1 += f1.x + f1.y;
        }
        s0 += __shfl_xor_sync(0xffffffffu, s0, 1);
        s0 += __shfl_xor_sync(0xffffffffu, s0, 2);
        s1 += __shfl_xor_sync(0xffffffffu, s1, 1);
        s1 += __shfl_xor_sync(0xffffffffu, s1, 2);
        float inv0 = 1.0f / s0, inv1 = 1.0f / s1;
        uint32_t ih0 = pack_h_f(inv0, inv0);
        uint32_t ih1 = pack_h_f(inv1, inv1);

        // O = P * V^T  (double-buffered Vt fragments, flattened kt x ne2 loop)
        float o[8][4];
#pragma unroll
        for (int ne = 0; ne < 8; ne++)
            o[ne][0] = o[ne][1] = o[ne][2] = o[ne][3] = 0.f;

        const int rbv = (seg >> 1) * 8 + (lane & 7);
        const int cov = (seg & 1) * 8;
        uint32_t v4[2][4];
        LDSM4(v4[0], smem_u32(&fsm[FVT + rbv * VTS + cov]));
#pragma unroll
        for (int kt = 0; kt < 13; kt++) {
            uint32_t pa[4];
            pa[0] = hmul2_u(ph[2 * kt][0], ih0);
            pa[1] = hmul2_u(ph[2 * kt][1], ih1);
            pa[2] = hmul2_u(ph[2 * kt + 1][0], ih0);
            pa[3] = hmul2_u(ph[2 * kt + 1][1], ih1);
#pragma unroll
            for (int ne2 = 0; ne2 < 4; ne2++) {
                const int li = kt * 4 + ne2;
                if (li < 51) {
                    const int nx = li + 1;
                    int r = (nx & 3) * 16 + rbv;
                    int co = (nx >> 2) * 16 + cov;
                    LDSM4(v4[(li + 1) & 1], smem_u32(&fsm[FVT + r * VTS + co]));
                }
                mma_f16(o[2 * ne2 + 0], pa, v4[li & 1] + 0);
                mma_f16(o[2 * ne2 + 1], pa, v4[li & 1] + 2);
            }
        }

        // epilogue: residual add, guarded stores
        int r0 = mt * 16 + (lane >> 2);
        int cb = (lane & 3) * 2;
        if (r0 < SEQL) {
            size_t base = ((size_t)b * SEQL + r0) * HD + h * DH;
#pragma unroll
            for (int ne = 0; ne < 8; ne++) {
                int n = ne * 8 + cb;
                float2 t = *(const float2*)(g_tokens + base + n);
                float2 ov = {t.x + o[ne][0], t.y + o[ne][1]};
                *(float2*)(out + base + n) = ov;
            }
        }
        if (r0 + 8 < SEQL) {
            size_t base = ((size_t)b * SEQL + r0 + 8) * HD + h * DH;
#pragma unroll
            for (int ne = 0; ne < 8; ne++) {
                int n = ne * 8 + cb;
                float2 t = *(const float2*)(g_tokens + base + n);
                float2 ov = {t.x + o[ne][2], t.y + o[ne][3]};
                *(float2*)(out + base + n) = ov;
            }
        }
    }
}

// ---------------- launcher ----------------
extern "C" void kernel_launch(void* const* d_in, const int* in_sizes, int n_in,
                              void* d_out, int out_size) {
    const float* images = (const float*)d_in[0];
    const float* W_map  = (const float*)d_in[1];
    const float* b_map  = (const float*)d_in[2];
    const float* cls    = (const float*)d_in[3];
    const float* ln_w   = (const float*)d_in[4];
    const float* ln_b   = (const float*)d_in[5];
    const float* Wq     = (const float*)d_in[6];
    const float* bq     = (const float*)d_in[7];
    const float* Wk     = (const float*)d_in[8];
    const float* bk     = (const float*)d_in[9];
    const float* Wv     = (const float*)d_in[10];
    const float* bv     = (const float*)d_in[11];
    float* out = (float*)d_out;

    cudaFuncSetAttribute(gemm_tokens_mma, cudaFuncAttributeMaxDynamicSharedMemorySize, G_SMEM);
    cudaFuncSetAttribute(qkv_attn_fused, cudaFuncAttributeMaxDynamicSharedMemorySize, FUSED_SMEM);

    pos_kernel<<<(SEQL * HD + 255) / 256, 256>>>();
    cls_kernel<<<NB, 256>>>(cls);
    cvt_kernel<<<4736, 256>>>(images, W_map);
    gemm_tokens_mma<<<dim3(HD / 128, (NB * NPAT) / 128), 256, G_SMEM>>>(b_map);
    stats_kernel<<<NB, 1024>>>();
    qkv_attn_fused<<<NB * NH, NTH, FUSED_SMEM>>>(ln_w, ln_b, Wq, bq, Wk, bk, Wv, bv, out);
}